// round 3
// baseline (speedup 1.0000x reference)
#include <cuda_runtime.h>
#include <math.h>

#define NB 16384
#define NIN 128
#define NH 512
#define NY 32
#define NK 8

static __device__ float g_feat[NB * NH];     // 32 MB scratch
static __device__ float g_invD2[NB * NY];    // 2 MB
static __device__ float g_V[NB * NY * NK];   // 16 MB

__device__ __forceinline__ float softplus_f(float v) {
    return (v > 20.f) ? v : log1pf(expf(v));
}

// ---------------------------------------------------------------------------
// K1: feat = relu(x @ W1 + b1)   [16384,128] @ [128,512] -> [16384,512]
// tile 64x64, 256 threads, 4x4 micro-tile, K chunks of 32
// ---------------------------------------------------------------------------
__global__ void __launch_bounds__(256) feat_kernel(const float* __restrict__ x,
                                                   const float* __restrict__ W1,
                                                   const float* __restrict__ b1) {
    __shared__ float Xs[32][68];   // [k][m], row = 272B (16B aligned)
    __shared__ float Ws[32][68];   // [k][n]
    const int bm = blockIdx.y * 64;
    const int bn = blockIdx.x * 64;
    const int tid = threadIdx.x;
    const int tx = tid & 15, ty = tid >> 4;

    float acc[4][4];
#pragma unroll
    for (int i = 0; i < 4; i++)
#pragma unroll
        for (int jj = 0; jj < 4; jj++) acc[i][jj] = 0.f;

    for (int k0 = 0; k0 < NIN; k0 += 32) {
#pragma unroll
        for (int t = 0; t < 8; t++) {
            int idx = tid + t * 256;
            int m = idx >> 5, k = idx & 31;
            Xs[k][m] = x[(size_t)(bm + m) * NIN + k0 + k];
        }
#pragma unroll
        for (int t = 0; t < 8; t++) {
            int idx = tid + t * 256;
            int k = idx >> 6, n = idx & 63;
            Ws[k][n] = W1[(size_t)(k0 + k) * NH + bn + n];
        }
        __syncthreads();
#pragma unroll
        for (int k = 0; k < 32; k++) {
            float4 a  = *(const float4*)&Xs[k][ty * 4];
            float4 bq = *(const float4*)&Ws[k][tx * 4];
            float av[4] = {a.x, a.y, a.z, a.w};
            float bv[4] = {bq.x, bq.y, bq.z, bq.w};
#pragma unroll
            for (int i = 0; i < 4; i++)
#pragma unroll
                for (int jj = 0; jj < 4; jj++)
                    acc[i][jj] = fmaf(av[i], bv[jj], acc[i][jj]);
        }
        __syncthreads();
    }
#pragma unroll
    for (int i = 0; i < 4; i++) {
        int m = bm + ty * 4 + i;
#pragma unroll
        for (int jj = 0; jj < 4; jj++) {
            int n = bn + tx * 4 + jj;
            float v = acc[i][jj] + b1[n];
            g_feat[(size_t)m * NH + n] = fmaxf(v, 0.f);
        }
    }
}

// ---------------------------------------------------------------------------
// K2: head GEMM.  mode 0: invD2 = 1/(softplus(feat@WD+bD)+1e-3)^2  (N=32)
//                 mode 1: V = feat@WV+bV                           (N=256)
// tile 128x32, 256 threads, 4x4 micro-tile, K chunks of 32 (K=512)
// ---------------------------------------------------------------------------
__global__ void __launch_bounds__(256) head_kernel(const float* __restrict__ Wmat,
                                                   const float* __restrict__ bias,
                                                   int N, int mode) {
    __shared__ float Fs[32][132];   // [k][m], row = 528B
    __shared__ float Ws2[32][36];   // [k][n], row = 144B
    const int bm = blockIdx.y * 128;
    const int bn = blockIdx.x * 32;
    const int tid = threadIdx.x;
    const int tx = tid & 7, ty = tid >> 3;

    float acc[4][4];
#pragma unroll
    for (int i = 0; i < 4; i++)
#pragma unroll
        for (int jj = 0; jj < 4; jj++) acc[i][jj] = 0.f;

    for (int k0 = 0; k0 < NH; k0 += 32) {
#pragma unroll
        for (int t = 0; t < 16; t++) {          // 128*32 / 256
            int idx = tid + t * 256;
            int m = idx >> 5, k = idx & 31;
            Fs[k][m] = g_feat[(size_t)(bm + m) * NH + k0 + k];
        }
#pragma unroll
        for (int t = 0; t < 4; t++) {           // 32*32 / 256
            int idx = tid + t * 256;
            int k = idx >> 5, n = idx & 31;
            Ws2[k][n] = Wmat[(size_t)(k0 + k) * N + bn + n];
        }
        __syncthreads();
#pragma unroll
        for (int k = 0; k < 32; k++) {
            float4 a  = *(const float4*)&Fs[k][ty * 4];
            float4 bq = *(const float4*)&Ws2[k][tx * 4];
            float av[4] = {a.x, a.y, a.z, a.w};
            float bv[4] = {bq.x, bq.y, bq.z, bq.w};
#pragma unroll
            for (int i = 0; i < 4; i++)
#pragma unroll
                for (int jj = 0; jj < 4; jj++)
                    acc[i][jj] = fmaf(av[i], bv[jj], acc[i][jj]);
        }
        __syncthreads();
    }
#pragma unroll
    for (int i = 0; i < 4; i++) {
        int m = bm + ty * 4 + i;
#pragma unroll
        for (int jj = 0; jj < 4; jj++) {
            int n = bn + tx * 4 + jj;
            float v = acc[i][jj] + bias[n];
            if (mode == 0) {
                float d = softplus_f(v) + 1e-3f;
                g_invD2[(size_t)m * NY + n] = 1.f / (d * d);
            } else {
                g_V[(size_t)m * (NY * NK) + n] = v;
            }
        }
    }
}

// ---------------------------------------------------------------------------
// K3: per-batch Woodbury build + Jacobi eig + sqrtm reconstruction.
// One warp per 32x32 matrix, 4 warps per block.
// ---------------------------------------------------------------------------
__global__ void __launch_bounds__(128) sqrtm_kernel(float* __restrict__ out) {
    __shared__ float Ash[4][32][33];
    __shared__ float Qsh[4][32][33];
    __shared__ float svsh[4][32];
    const int w = threadIdx.x >> 5;
    const int j = threadIdx.x & 31;     // lane
    const int b = blockIdx.x * 4 + w;

    float (*A)[33] = Ash[w];
    float (*Q)[33] = Qsh[w];
    float* svs = svsh[w];
    // prologue scratch overlaid on the (not-yet-needed) Q buffer
    float* scratch = &Qsh[w][0][0];
    float* Vs = scratch;          // 32x8
    float* Ww = scratch + 256;    // 32x8
    float* Mm = scratch + 512;    // 8x8 (becomes Cholesky L)
    float* Mi = scratch + 576;    // 8x8 M^-1

    // ---- load V row + invD2, build W = V * invD2 -------------------------
    const float invd2 = g_invD2[(size_t)b * NY + j];
    const float4 v0 = *(const float4*)&g_V[(size_t)b * 256 + j * 8];
    const float4 v1 = *(const float4*)&g_V[(size_t)b * 256 + j * 8 + 4];
    float vr[8] = {v0.x, v0.y, v0.z, v0.w, v1.x, v1.y, v1.z, v1.w};
#pragma unroll
    for (int k = 0; k < 8; k++) {
        Vs[j * 8 + k] = vr[k];
        Ww[j * 8 + k] = vr[k] * invd2;
    }
    __syncwarp();

    // ---- M = I + V^T W (8x8), 2 entries per lane -------------------------
#pragma unroll
    for (int e2 = 0; e2 < 2; e2++) {
        int e = j + e2 * 32;
        int kk = e >> 3, jj = e & 7;
        float s = (kk == jj) ? 1.f : 0.f;
        for (int y = 0; y < 32; y++)
            s = fmaf(Vs[y * 8 + kk], Ww[y * 8 + jj], s);
        Mm[e] = s;
    }
    __syncwarp();

    // ---- Cholesky M = L L^T (lane 0, fully unrolled) ---------------------
    if (j == 0) {
#pragma unroll
        for (int i = 0; i < 8; i++) {
#pragma unroll
            for (int m = 0; m < i; m++) {
                float sum = Mm[i * 8 + m];
#pragma unroll
                for (int t = 0; t < m; t++) sum -= Mm[i * 8 + t] * Mm[m * 8 + t];
                Mm[i * 8 + m] = sum / Mm[m * 8 + m];
            }
            float sum = Mm[i * 8 + i];
#pragma unroll
            for (int t = 0; t < i; t++) sum -= Mm[i * 8 + t] * Mm[i * 8 + t];
            Mm[i * 8 + i] = sqrtf(sum);
        }
    }
    __syncwarp();

    // ---- M^-1 via two triangular solves, one column per lane (0..7) ------
    if (j < 8) {
        float yv[8], zv[8];
#pragma unroll
        for (int i = 0; i < 8; i++) {
            float sum = (i == j) ? 1.f : 0.f;
#pragma unroll
            for (int m = 0; m < i; m++) sum -= Mm[i * 8 + m] * yv[m];
            yv[i] = sum / Mm[i * 8 + i];
        }
#pragma unroll
        for (int i = 7; i >= 0; i--) {
            float sum = yv[i];
#pragma unroll
            for (int m = i + 1; m < 8; m++) sum -= Mm[m * 8 + i] * zv[m];
            zv[i] = sum / Mm[i * 8 + i];
        }
#pragma unroll
        for (int i = 0; i < 8; i++) Mi[i * 8 + j] = zv[i];
    }
    __syncwarp();

    // ---- T = W_row_j @ Minv, then Sigma_inv row j into A -----------------
    float T[8];
#pragma unroll
    for (int jj = 0; jj < 8; jj++) {
        float s = 0.f;
#pragma unroll
        for (int kk = 0; kk < 8; kk++)
            s = fmaf(vr[kk] * invd2, Mi[kk * 8 + jj], s);
        T[jj] = s;
    }
    float ss = 0.f;
    for (int z = 0; z < 32; z++) {
        float s = 0.f;
#pragma unroll
        for (int kk = 0; kk < 8; kk++) s = fmaf(T[kk], Ww[z * 8 + kk], s);
        float val = ((z == j) ? invd2 : 0.f) - s;
        A[j][z] = val;
        ss = fmaf(val, val, ss);
    }
#pragma unroll
    for (int o = 16; o > 0; o >>= 1) ss += __shfl_xor_sync(0xffffffffu, ss, o);
    const float tol = fmaxf(1e-7f * sqrtf(ss), 1e-30f);
    __syncwarp();
    // init Q = I (overwrites prologue scratch)
    for (int z = 0; z < 32; z++) Q[j][z] = (z == j) ? 1.f : 0.f;
    __syncwarp();

    // ---- cyclic Jacobi: fused symmetric single-pass update ---------------
    for (int sweep = 0; sweep < 16; sweep++) {
        int nrot = 0;
        for (int p = 0; p < 31; p++) {
            for (int q = p + 1; q < 32; q++) {
                float apq = A[p][q];
                if (fabsf(apq) <= tol) continue;   // warp-uniform decision
                nrot++;
                float app = A[p][p];
                float aqq = A[q][q];
                float tau = (aqq - app) / (2.f * apq);
                float t = copysignf(1.f, tau) / (fabsf(tau) + sqrtf(fmaf(tau, tau, 1.f)));
                float c = 1.f / sqrtf(fmaf(t, t, 1.f));
                float s = t * c;
                float ajp = A[j][p], ajq = A[j][q];
                float qjp = Q[j][p], qjq = Q[j][q];
                __syncwarp();
                float np = c * ajp - s * ajq;
                float nq = s * ajp + c * ajq;
                np = (j == p) ? fmaf(-t, apq, app) : ((j == q) ? 0.f : np);
                nq = (j == q) ? fmaf( t, apq, aqq) : ((j == p) ? 0.f : nq);
                A[j][p] = np; A[j][q] = nq;     // column update
                A[p][j] = np; A[q][j] = nq;     // symmetric row mirror
                Q[j][p] = c * qjp - s * qjq;    // Q <- Q J
                Q[j][q] = s * qjp + c * qjq;
                __syncwarp();
            }
        }
        if (nrot == 0) break;
    }

    // ---- reconstruct: out = (Q diag((lam+eps)^{1/4}))(...)^T -------------
    svs[j] = sqrtf(sqrtf(fmaxf(A[j][j] + 1e-6f, 0.f)));
    __syncwarp();
    for (int k = 0; k < 32; k++) Q[j][k] *= svs[k];   // own row only
    __syncwarp();

    float accO[32];
#pragma unroll
    for (int i = 0; i < 32; i++) accO[i] = 0.f;
    for (int k = 0; k < 32; k++) {
        float qjk = Q[j][k];                           // stride-33: conflict-free
#pragma unroll
        for (int i = 0; i < 32; i++)
            accO[i] = fmaf(Q[i][k], qjk, accO[i]);     // broadcast loads
    }
    __syncwarp();
#pragma unroll
    for (int i = 0; i < 32; i++) A[j][i] = accO[i];    // row j (symmetric)
    __syncwarp();

    float* ob = out + (size_t)b * 1024;
#pragma unroll
    for (int t = 0; t < 8; t++) {                      // coalesced 512B stores
        int idx = t * 128 + j * 4;
        int rr = idx >> 5, cc = idx & 31;
        float4 val = make_float4(A[rr][cc], A[rr][cc + 1], A[rr][cc + 2], A[rr][cc + 3]);
        *(float4*)&ob[idx] = val;
    }
}

// ---------------------------------------------------------------------------
extern "C" void kernel_launch(void* const* d_in, const int* in_sizes, int n_in,
                              void* d_out, int out_size) {
    const float* x  = (const float*)d_in[0];
    const float* W1 = (const float*)d_in[1];
    const float* b1 = (const float*)d_in[2];
    const float* WD = (const float*)d_in[3];
    const float* bD = (const float*)d_in[4];
    const float* WV = (const float*)d_in[5];
    const float* bV = (const float*)d_in[6];
    float* out = (float*)d_out;

    dim3 g1(NH / 64, NB / 64);            // 8 x 256
    feat_kernel<<<g1, 256>>>(x, W1, b1);

    dim3 g2a(1, NB / 128);                // WD: N=32
    head_kernel<<<g2a, 256>>>(WD, bD, 32, 0);

    dim3 g2b((NY * NK) / 32, NB / 128);   // WV: N=256
    head_kernel<<<g2b, 256>>>(WV, bV, 256, 1);

    sqrtm_kernel<<<NB / 4, 128>>>(out);
}

// round 4
// speedup vs baseline: 4.0882x; 4.0882x over previous
#include <cuda_runtime.h>
#include <math.h>

#define NB 16384
#define NIN 128
#define NH 512
#define NY 32
#define NK 8

static __device__ float g_feat[NB * NH];     // 32 MB scratch
static __device__ float g_D[NB * NY];        // 2 MB  (D = softplus+1e-3)
static __device__ float g_V[NB * NY * NK];   // 16 MB

typedef unsigned long long ull;

__device__ __forceinline__ ull pack2(float lo, float hi) {
    ull r; asm("mov.b64 %0, {%1, %2};" : "=l"(r) : "f"(lo), "f"(hi)); return r;
}
__device__ __forceinline__ void unpack2(ull v, float& lo, float& hi) {
    asm("mov.b64 {%0, %1}, %2;" : "=f"(lo), "=f"(hi) : "l"(v));
}
__device__ __forceinline__ ull fma2_(ull a, ull b, ull c) {
    ull d; asm("fma.rn.f32x2 %0, %1, %2, %3;" : "=l"(d) : "l"(a), "l"(b), "l"(c)); return d;
}
__device__ __forceinline__ ull mul2_(ull a, ull b) {
    ull d; asm("mul.rn.f32x2 %0, %1, %2;" : "=l"(d) : "l"(a), "l"(b)); return d;
}

__device__ __forceinline__ float softplus_f(float v) {
    return (v > 20.f) ? v : log1pf(expf(v));
}

// ---------------------------------------------------------------------------
// K1: feat = relu(x @ W1 + b1)   [16384,128] @ [128,512]
// ---------------------------------------------------------------------------
__global__ void __launch_bounds__(256) feat_kernel(const float* __restrict__ x,
                                                   const float* __restrict__ W1,
                                                   const float* __restrict__ b1) {
    __shared__ float Xs[32][68];
    __shared__ float Ws[32][68];
    const int bm = blockIdx.y * 64;
    const int bn = blockIdx.x * 64;
    const int tid = threadIdx.x;
    const int tx = tid & 15, ty = tid >> 4;

    float acc[4][4];
#pragma unroll
    for (int i = 0; i < 4; i++)
#pragma unroll
        for (int jj = 0; jj < 4; jj++) acc[i][jj] = 0.f;

    for (int k0 = 0; k0 < NIN; k0 += 32) {
#pragma unroll
        for (int t = 0; t < 8; t++) {
            int idx = tid + t * 256;
            int m = idx >> 5, k = idx & 31;
            Xs[k][m] = x[(size_t)(bm + m) * NIN + k0 + k];
        }
#pragma unroll
        for (int t = 0; t < 8; t++) {
            int idx = tid + t * 256;
            int k = idx >> 6, n = idx & 63;
            Ws[k][n] = W1[(size_t)(k0 + k) * NH + bn + n];
        }
        __syncthreads();
#pragma unroll
        for (int k = 0; k < 32; k++) {
            float4 a  = *(const float4*)&Xs[k][ty * 4];
            float4 bq = *(const float4*)&Ws[k][tx * 4];
            float av[4] = {a.x, a.y, a.z, a.w};
            float bv[4] = {bq.x, bq.y, bq.z, bq.w};
#pragma unroll
            for (int i = 0; i < 4; i++)
#pragma unroll
                for (int jj = 0; jj < 4; jj++)
                    acc[i][jj] = fmaf(av[i], bv[jj], acc[i][jj]);
        }
        __syncthreads();
    }
#pragma unroll
    for (int i = 0; i < 4; i++) {
        int m = bm + ty * 4 + i;
#pragma unroll
        for (int jj = 0; jj < 4; jj++) {
            int n = bn + tx * 4 + jj;
            float v = acc[i][jj] + b1[n];
            g_feat[(size_t)m * NH + n] = fmaxf(v, 0.f);
        }
    }
}

// ---------------------------------------------------------------------------
// K2: head GEMM. mode 0: D = softplus(feat@WD+bD)+1e-3  (N=32)
//                mode 1: V = feat@WV+bV                 (N=256)
// ---------------------------------------------------------------------------
__global__ void __launch_bounds__(256) head_kernel(const float* __restrict__ Wmat,
                                                   const float* __restrict__ bias,
                                                   int N, int mode) {
    __shared__ float Fs[32][132];
    __shared__ float Ws2[32][36];
    const int bm = blockIdx.y * 128;
    const int bn = blockIdx.x * 32;
    const int tid = threadIdx.x;
    const int tx = tid & 7, ty = tid >> 3;

    float acc[4][4];
#pragma unroll
    for (int i = 0; i < 4; i++)
#pragma unroll
        for (int jj = 0; jj < 4; jj++) acc[i][jj] = 0.f;

    for (int k0 = 0; k0 < NH; k0 += 32) {
#pragma unroll
        for (int t = 0; t < 16; t++) {
            int idx = tid + t * 256;
            int m = idx >> 5, k = idx & 31;
            Fs[k][m] = g_feat[(size_t)(bm + m) * NH + k0 + k];
        }
#pragma unroll
        for (int t = 0; t < 4; t++) {
            int idx = tid + t * 256;
            int k = idx >> 5, n = idx & 31;
            Ws2[k][n] = Wmat[(size_t)(k0 + k) * N + bn + n];
        }
        __syncthreads();
#pragma unroll
        for (int k = 0; k < 32; k++) {
            float4 a  = *(const float4*)&Fs[k][ty * 4];
            float4 bq = *(const float4*)&Ws2[k][tx * 4];
            float av[4] = {a.x, a.y, a.z, a.w};
            float bv[4] = {bq.x, bq.y, bq.z, bq.w};
#pragma unroll
            for (int i = 0; i < 4; i++)
#pragma unroll
                for (int jj = 0; jj < 4; jj++)
                    acc[i][jj] = fmaf(av[i], bv[jj], acc[i][jj]);
        }
        __syncthreads();
    }
#pragma unroll
    for (int i = 0; i < 4; i++) {
        int m = bm + ty * 4 + i;
#pragma unroll
        for (int jj = 0; jj < 4; jj++) {
            int n = bn + tx * 4 + jj;
            float v = acc[i][jj] + bias[n];
            if (mode == 0) {
                g_D[(size_t)m * NY + n] = softplus_f(v) + 1e-3f;
            } else {
                g_V[(size_t)m * (NY * NK) + n] = v;
            }
        }
    }
}

// ---------------------------------------------------------------------------
// K3: one-sided Jacobi SVD of G = [diag(D); V^T] (40x32), all in registers.
// Sigma = G^T G  =>  Sigma_inv_sqrt = W diag(sqrt(1/s^2 + eps)) W^T.
// One warp per matrix; lane j owns column g_j packed as 20 f32x2 registers.
// ---------------------------------------------------------------------------
__global__ void __launch_bounds__(128, 4) jacobi_kernel(float* __restrict__ out) {
    __shared__ float Dsh[4][32];
    __shared__ float Vsh[4][32][8];
    __shared__ float Qsh[4][32][33];

    const int w = threadIdx.x >> 5;
    const int j = threadIdx.x & 31;
    const int b = blockIdx.x * 4 + w;

    // ---- load D_j and V row j; init column g_j = [D_j e_j ; V[j][:]] -----
    const float Dj = g_D[(size_t)b * NY + j];
    const float4 v0 = *(const float4*)&g_V[(size_t)b * 256 + j * 8];
    const float4 v1 = *(const float4*)&g_V[(size_t)b * 256 + j * 8 + 4];
    Dsh[w][j] = Dj;
    Vsh[w][j][0] = v0.x; Vsh[w][j][1] = v0.y; Vsh[w][j][2] = v0.z; Vsh[w][j][3] = v0.w;
    Vsh[w][j][4] = v1.x; Vsh[w][j][5] = v1.y; Vsh[w][j][6] = v1.z; Vsh[w][j][7] = v1.w;

    ull gp[20];
#pragma unroll
    for (int i = 0; i < 16; i++) {
        float lo = (2 * i     == j) ? Dj : 0.f;
        float hi = (2 * i + 1 == j) ? Dj : 0.f;
        gp[i] = pack2(lo, hi);
    }
    gp[16] = pack2(v0.x, v0.y); gp[17] = pack2(v0.z, v0.w);
    gp[18] = pack2(v1.x, v1.y); gp[19] = pack2(v1.z, v1.w);

    float nrm = Dj * Dj;
    nrm = fmaf(v0.x, v0.x, nrm); nrm = fmaf(v0.y, v0.y, nrm);
    nrm = fmaf(v0.z, v0.z, nrm); nrm = fmaf(v0.w, v0.w, nrm);
    nrm = fmaf(v1.x, v1.x, nrm); nrm = fmaf(v1.y, v1.y, nrm);
    nrm = fmaf(v1.z, v1.z, nrm); nrm = fmaf(v1.w, v1.w, nrm);

    const float tol2 = 1.6e-13f;   // (4e-7)^2, relative criterion

    // ---- one-sided Jacobi sweeps (tournament: 31 rounds x 16 pairs) ------
    for (int sweep = 0; sweep < 14; sweep++) {
        int did = 0;
        for (int r = 0; r < 31; r++) {
            // round-robin partner: fixed player 31 pairs with r
            int partner;
            if (j == 31) partner = r;
            else {
                int m = 2 * r - j;
                m = (m < 0) ? m + 31 : ((m >= 31) ? m - 31 : m);
                partner = (m == j) ? 31 : m;
            }
            // fetch partner column via shuffles
            ull hp[20];
#pragma unroll
            for (int i = 0; i < 20; i++)
                hp[i] = __shfl_sync(0xffffffffu, gp[i], partner);
            float nrmo = __shfl_sync(0xffffffffu, nrm, partner);

            // a_pq = g_j . g_partner  (identical on both lanes of the pair)
            ull acc0 = 0ull, acc1 = 0ull;
#pragma unroll
            for (int i = 0; i < 20; i += 2) {
                acc0 = fma2_(gp[i],     hp[i],     acc0);
                acc1 = fma2_(gp[i + 1], hp[i + 1], acc1);
            }
            float alo, ahi, blo, bhi;
            unpack2(acc0, alo, ahi); unpack2(acc1, blo, bhi);
            float apq = (alo + blo) + (ahi + bhi);

            bool rot = apq * apq > tol2 * nrm * nrmo;
            if (__any_sync(0xffffffffu, rot)) {
                did = 1;
                bool isp = j < partner;                 // role: p = lower lane
                float dn = isp ? (nrmo - nrm) : (nrm - nrmo);   // a_qq - a_pp
                float tau = dn / (2.f * apq);
                float t = copysignf(1.f, tau) / (fabsf(tau) + sqrtf(fmaf(tau, tau, 1.f)));
                if (!rot) t = 0.f;
                float c = rsqrtf(fmaf(t, t, 1.f));
                float s = t * c;
                float sg = isp ? -s : s;
                ull c2 = pack2(c, c), sg2 = pack2(sg, sg);
#pragma unroll
                for (int i = 0; i < 20; i++)
                    gp[i] = fma2_(c2, gp[i], mul2_(sg2, hp[i]));
                nrm = fmaf(isp ? -t : t, apq, nrm);
            }
        }
        if (!did) break;
    }

    // ---- epilogue: recover eigenvalues + eigenvectors --------------------
    float gf[40];
#pragma unroll
    for (int i = 0; i < 20; i++) unpack2(gp[i], gf[2 * i], gf[2 * i + 1]);

    float s2 = 0.f;
#pragma unroll
    for (int i = 0; i < 40; i++) s2 = fmaf(gf[i], gf[i], s2);
    const float lam = 1.f / s2;                 // eigenvalue of Sigma_inv
    const float fj = sqrtf(lam + 1e-6f);        // sqrt(eig + EPS)

    __syncwarp();
    // w_raw = G^T g_final = Sigma w = s2 * w  (uses original sparse G)
    float wv[32];
    float nn = 0.f;
#pragma unroll
    for (int i = 0; i < 32; i++) {
        float sacc = Dsh[w][i] * gf[i];
#pragma unroll
        for (int k = 0; k < 8; k++)
            sacc = fmaf(Vsh[w][i][k], gf[32 + k], sacc);
        wv[i] = sacc;
        nn = fmaf(sacc, sacc, nn);
    }
    const float scale = sqrtf(fj) * rsqrtf(nn); // q_j = w * sqrt(f)/||w||
#pragma unroll
    for (int i = 0; i < 32; i++)
        Qsh[w][i][j] = wv[i] * scale;           // column j, conflict-free
    __syncwarp();

    // ---- out = Q Q^T (row j per lane) ------------------------------------
    float accO[32];
#pragma unroll
    for (int i = 0; i < 32; i++) accO[i] = 0.f;
    for (int k = 0; k < 32; k++) {
        float qjk = Qsh[w][j][k];               // stride-33: conflict-free
#pragma unroll
        for (int i = 0; i < 32; i++)
            accO[i] = fmaf(Qsh[w][i][k], qjk, accO[i]);  // broadcast loads
    }
    __syncwarp();
#pragma unroll
    for (int i = 0; i < 32; i++) Qsh[w][j][i] = accO[i];  // stage row j
    __syncwarp();

    float* ob = out + (size_t)b * 1024;
#pragma unroll
    for (int t = 0; t < 8; t++) {               // coalesced 512B stores
        int idx = t * 128 + j * 4;
        int rr = idx >> 5, cc = idx & 31;
        float4 val = make_float4(Qsh[w][rr][cc], Qsh[w][rr][cc + 1],
                                 Qsh[w][rr][cc + 2], Qsh[w][rr][cc + 3]);
        *(float4*)&ob[idx] = val;
    }
}

// ---------------------------------------------------------------------------
extern "C" void kernel_launch(void* const* d_in, const int* in_sizes, int n_in,
                              void* d_out, int out_size) {
    const float* x  = (const float*)d_in[0];
    const float* W1 = (const float*)d_in[1];
    const float* b1 = (const float*)d_in[2];
    const float* WD = (const float*)d_in[3];
    const float* bD = (const float*)d_in[4];
    const float* WV = (const float*)d_in[5];
    const float* bV = (const float*)d_in[6];
    float* out = (float*)d_out;

    dim3 g1(NH / 64, NB / 64);
    feat_kernel<<<g1, 256>>>(x, W1, b1);

    dim3 g2a(1, NB / 128);
    head_kernel<<<g2a, 256>>>(WD, bD, 32, 0);

    dim3 g2b((NY * NK) / 32, NB / 128);
    head_kernel<<<g2b, 256>>>(WV, bV, 256, 1);

    jacobi_kernel<<<NB / 4, 128>>>(out);
}